// round 3
// baseline (speedup 1.0000x reference)
#include <cuda_runtime.h>
#include <cuda_bf16.h>

#define NN 25000
#define NR 16
#define NH 64
#define NC 16
#define NE 800000

// ---- scratch (allocation-free: __device__ globals) ----
__device__ float g_x[NN * NH];                 // layer-1 output x = relu(agg1+root1+b1)
__device__ float g_h[(size_t)NR * NN * NC];    // per-relation transformed nodes
__device__ int   g_rowidx[NE];                 // rel*NN + src (row into W1 and into h)
__device__ int   g_dst[NE];
__device__ int   g_deg[NN];
__device__ int   g_off[NN + 1];
__device__ int   g_cur[NN];
__device__ int   g_csr[NE];                    // rowidx grouped by dst
__device__ int   g_is64;

// ---------------------------------------------------------------------------
// Detect whether edge_index arrived as int64 or int32 (jax x64 ambiguity).
__global__ void k_detect(const void* ei) {
    const unsigned long long* p = (const unsigned long long*)ei;
    unsigned long long acc = 0;
#pragma unroll
    for (int i = 0; i < 64; i++) acc |= (p[i] >> 32);
    g_is64 = (acc == 0ull) ? 1 : 0;
}

__global__ void k_zero() {
    int i = blockIdx.x * blockDim.x + threadIdx.x;
    if (i < NN) g_deg[i] = 0;
}

// Convert edge metadata into packed ints + histogram dst degrees.
__global__ void k_convert(const void* ei, const void* et) {
    int e = blockIdx.x * blockDim.x + threadIdx.x;
    if (e >= NE) return;
    int src, dst, r;
    if (g_is64) {
        const long long* E = (const long long*)ei;
        const long long* T = (const long long*)et;
        src = (int)E[e]; dst = (int)E[NE + e]; r = (int)T[e];
    } else {
        const int* E = (const int*)ei;
        const int* T = (const int*)et;
        src = E[e]; dst = E[NE + e]; r = T[e];
    }
    g_rowidx[e] = r * NN + src;
    g_dst[e]    = dst;
    atomicAdd(&g_deg[dst], 1);
}

// Single-block exclusive scan of g_deg -> g_off (and g_cur copy).
__global__ void k_scan() {
    __shared__ int warp_sums[32];
    __shared__ int s_carry;
    int tid  = threadIdx.x;            // 1024 threads
    int lane = tid & 31;
    int wid  = tid >> 5;
    if (tid == 0) s_carry = 0;
    __syncthreads();
    for (int base = 0; base < NN; base += 1024) {
        int idx = base + tid;
        int v = (idx < NN) ? g_deg[idx] : 0;
        // warp inclusive scan
        int incl = v;
#pragma unroll
        for (int d = 1; d < 32; d <<= 1) {
            int t = __shfl_up_sync(0xFFFFFFFFu, incl, d);
            if (lane >= d) incl += t;
        }
        if (lane == 31) warp_sums[wid] = incl;
        __syncthreads();
        if (wid == 0) {
            int ws = warp_sums[lane];
#pragma unroll
            for (int d = 1; d < 32; d <<= 1) {
                int t = __shfl_up_sync(0xFFFFFFFFu, ws, d);
                if (lane >= d) ws += t;
            }
            warp_sums[lane] = ws;
        }
        __syncthreads();
        int excl = incl - v + (wid > 0 ? warp_sums[wid - 1] : 0) + s_carry;
        if (idx < NN) { g_off[idx] = excl; g_cur[idx] = excl; }
        __syncthreads();
        if (tid == 1023) s_carry = excl + v;
        __syncthreads();
    }
    if (tid == 0) g_off[NN] = s_carry;
}

// Scatter rowidx into CSR order (grouped by dst).
__global__ void k_scatter() {
    int e = blockIdx.x * blockDim.x + threadIdx.x;
    if (e >= NE) return;
    int pos = atomicAdd(&g_cur[g_dst[e]], 1);
    g_csr[pos] = g_rowidx[e];
}

// Layer-1 aggregation, no atomics: 16 threads per dst, register accumulation.
// x[dst] = relu( sum_{e in dst} W1[rowidx_e] + root1[dst] + b1 )
__global__ void k_agg1(const float* __restrict__ W1,
                       const float* __restrict__ root1,
                       const float* __restrict__ b1) {
    int g = blockIdx.x * (blockDim.x >> 4) + (threadIdx.x >> 4);  // dst node
    int s = threadIdx.x & 15;                                     // 16B chunk
    if (g >= NN) return;
    int beg = g_off[g], end = g_off[g + 1];

    float4 acc = make_float4(0.f, 0.f, 0.f, 0.f);
    int i = beg;
    for (; i + 4 <= end; i += 4) {
        int r0 = g_csr[i], r1 = g_csr[i + 1], r2 = g_csr[i + 2], r3 = g_csr[i + 3];
        float4 v0 = __ldg((const float4*)(W1 + (long)r0 * NH) + s);
        float4 v1 = __ldg((const float4*)(W1 + (long)r1 * NH) + s);
        float4 v2 = __ldg((const float4*)(W1 + (long)r2 * NH) + s);
        float4 v3 = __ldg((const float4*)(W1 + (long)r3 * NH) + s);
        acc.x += v0.x + v1.x + v2.x + v3.x;
        acc.y += v0.y + v1.y + v2.y + v3.y;
        acc.z += v0.z + v1.z + v2.z + v3.z;
        acc.w += v0.w + v1.w + v2.w + v3.w;
    }
    for (; i < end; i++) {
        int r0 = g_csr[i];
        float4 v0 = __ldg((const float4*)(W1 + (long)r0 * NH) + s);
        acc.x += v0.x; acc.y += v0.y; acc.z += v0.z; acc.w += v0.w;
    }
    float4 rt = __ldg((const float4*)(root1 + (long)g * NH) + s);
    float4 bb = __ldg((const float4*)b1 + s);
    acc.x = fmaxf(acc.x + rt.x + bb.x, 0.f);
    acc.y = fmaxf(acc.y + rt.y + bb.y, 0.f);
    acc.z = fmaxf(acc.z + rt.z + bb.z, 0.f);
    acc.w = fmaxf(acc.w + rt.w + bb.w, 0.f);
    *((float4*)(g_x + (long)g * NH) + s) = acc;
}

// h[r, n, c] = sum_h x[n,h] * W2[r,h,c].  grid = (nodeTiles, NR).
__global__ void k_h(const float* __restrict__ W2) {
    __shared__ float w2s[NH * NC];  // 4 KB: W2[r]
    int r = blockIdx.y;
    for (int i = threadIdx.x; i < NH * NC; i += blockDim.x)
        w2s[i] = W2[(long)r * NH * NC + i];
    __syncthreads();

    int c = threadIdx.x & 15;
    int n = blockIdx.x * 16 + (threadIdx.x >> 4);
    if (n >= NN) return;

    const float4* xr = (const float4*)(g_x + (long)n * NH);
    float acc = 0.0f;
#pragma unroll
    for (int h4 = 0; h4 < NH / 4; h4++) {
        float4 xv = __ldg(&xr[h4]);
        acc += xv.x * w2s[(h4 * 4 + 0) * NC + c];
        acc += xv.y * w2s[(h4 * 4 + 1) * NC + c];
        acc += xv.z * w2s[(h4 * 4 + 2) * NC + c];
        acc += xv.w * w2s[(h4 * 4 + 3) * NC + c];
    }
    g_h[((long)r * NN + n) * NC + c] = acc;
}

// Layer-2 aggregation + root + bias + log_softmax, fused. 16 threads per dst.
__global__ void k_agg2(const float* __restrict__ root2,
                       const float* __restrict__ b2,
                       float* __restrict__ out) {
    __shared__ float r2s[NH * NC];  // 4 KB
    for (int i = threadIdx.x; i < NH * NC; i += blockDim.x) r2s[i] = root2[i];
    __syncthreads();

    int g = blockIdx.x * (blockDim.x >> 4) + (threadIdx.x >> 4);
    int c = threadIdx.x & 15;
    if (g >= NN) return;
    int beg = g_off[g], end = g_off[g + 1];

    float acc = __ldg(b2 + c);
    int i = beg;
    for (; i + 4 <= end; i += 4) {
        int r0 = g_csr[i], r1 = g_csr[i + 1], r2 = g_csr[i + 2], r3 = g_csr[i + 3];
        float v0 = __ldg(g_h + (long)r0 * NC + c);
        float v1 = __ldg(g_h + (long)r1 * NC + c);
        float v2 = __ldg(g_h + (long)r2 * NC + c);
        float v3 = __ldg(g_h + (long)r3 * NC + c);
        acc += v0 + v1 + v2 + v3;
    }
    for (; i < end; i++)
        acc += __ldg(g_h + (long)g_csr[i] * NC + c);

    // + x[g] @ root2
    const float4* xr = (const float4*)(g_x + (long)g * NH);
#pragma unroll
    for (int h4 = 0; h4 < NH / 4; h4++) {
        float4 xv = __ldg(&xr[h4]);
        acc += xv.x * r2s[(h4 * 4 + 0) * NC + c];
        acc += xv.y * r2s[(h4 * 4 + 1) * NC + c];
        acc += xv.z * r2s[(h4 * 4 + 2) * NC + c];
        acc += xv.w * r2s[(h4 * 4 + 3) * NC + c];
    }

    // log_softmax across the 16 lanes of this half-warp
    unsigned mask = 0xFFFFu << (threadIdx.x & 16);
    float m = acc;
#pragma unroll
    for (int d = 8; d >= 1; d >>= 1) m = fmaxf(m, __shfl_xor_sync(mask, m, d));
    float ex = expf(acc - m);
    float sum = ex;
#pragma unroll
    for (int d = 8; d >= 1; d >>= 1) sum += __shfl_xor_sync(mask, sum, d);
    out[(long)g * NC + c] = acc - m - logf(sum);
}

extern "C" void kernel_launch(void* const* d_in, const int* in_sizes, int n_in,
                              void* d_out, int out_size) {
    const void*  edge_index = d_in[0];
    const void*  edge_type  = d_in[1];
    const float* W1         = (const float*)d_in[2];
    const float* root1      = (const float*)d_in[3];
    const float* b1         = (const float*)d_in[4];
    const float* W2         = (const float*)d_in[5];
    const float* root2      = (const float*)d_in[6];
    const float* b2         = (const float*)d_in[7];
    float* out = (float*)d_out;

    k_detect<<<1, 1>>>(edge_index);
    k_zero<<<(NN + 255) / 256, 256>>>();
    k_convert<<<(NE + 255) / 256, 256>>>(edge_index, edge_type);
    k_scan<<<1, 1024>>>();
    k_scatter<<<(NE + 255) / 256, 256>>>();
    k_agg1<<<(NN * 16 + 255) / 256, 256>>>(W1, root1, b1);
    {
        dim3 grid((NN + 15) / 16, NR);
        k_h<<<grid, 256>>>(W2);
    }
    k_agg2<<<(NN * 16 + 255) / 256, 256>>>(root2, b2, out);
}

// round 4
// speedup vs baseline: 1.0978x; 1.0978x over previous
#include <cuda_runtime.h>
#include <cuda_bf16.h>

#define NN 25000
#define NR 16
#define NH 64
#define NC 16
#define NE 800000
#define CHUNK 1000          // NN = 25 * 1000
#define NCHUNK 25

// ---- scratch (allocation-free: __device__ globals) ----
__device__ float g_x[NN * NH];                 // layer-1 output x = relu(agg1+root1+b1)
__device__ float g_h[(size_t)NR * NN * NC];    // per-relation transformed nodes
__device__ int   g_rowidx[NE];                 // rel*NN + src (row into W1 and into h)
__device__ int   g_dstv[NE];
__device__ int   g_lrank[NE];                  // rank of edge within its dst bucket
__device__ int   g_deg[NN];
__device__ int   g_offL[NN];                   // block-local exclusive scan of deg
__device__ int   g_bsum[NCHUNK];               // per-chunk totals
__device__ int   g_boff[NCHUNK];               // exclusive scan of chunk totals
__device__ int   g_csr[NE];                    // rowidx grouped by dst
__device__ int   g_is64;

__device__ __forceinline__ int final_off(int i) {
    return (i < NN) ? (g_offL[i] + g_boff[i / CHUNK]) : NE;
}

// ---------------------------------------------------------------------------
// Block 98: dtype detect.  Blocks 0..97: zero degree counters.
__global__ void k_pre(const void* ei) {
    if (blockIdx.x == gridDim.x - 1) {
        if (threadIdx.x == 0) {
            const unsigned long long* p = (const unsigned long long*)ei;
            unsigned long long acc = 0;
#pragma unroll
            for (int i = 0; i < 64; i++) acc |= (p[i] >> 32);
            g_is64 = (acc == 0ull) ? 1 : 0;
        }
        return;
    }
    int i = blockIdx.x * blockDim.x + threadIdx.x;
    if (i < NN) g_deg[i] = 0;
}

// Convert edge metadata into packed ints + histogram dst degrees + bucket rank.
__global__ void k_convert(const void* ei, const void* et) {
    int e = blockIdx.x * blockDim.x + threadIdx.x;
    if (e >= NE) return;
    int src, dst, r;
    if (g_is64) {
        const long long* E = (const long long*)ei;
        const long long* T = (const long long*)et;
        src = (int)E[e]; dst = (int)E[NE + e]; r = (int)T[e];
    } else {
        const int* E = (const int*)ei;
        const int* T = (const int*)et;
        src = E[e]; dst = E[NE + e]; r = T[e];
    }
    g_rowidx[e] = r * NN + src;
    g_dstv[e]   = dst;
    g_lrank[e]  = atomicAdd(&g_deg[dst], 1);
}

// Per-chunk local exclusive scan: 25 blocks x 1024 threads (1000 used each).
__global__ void k_scanA() {
    __shared__ int warp_sums[32];
    int tid  = threadIdx.x;
    int lane = tid & 31;
    int wid  = tid >> 5;
    int idx  = blockIdx.x * CHUNK + tid;
    int v = (tid < CHUNK) ? g_deg[idx] : 0;
    int incl = v;
#pragma unroll
    for (int d = 1; d < 32; d <<= 1) {
        int t = __shfl_up_sync(0xFFFFFFFFu, incl, d);
        if (lane >= d) incl += t;
    }
    if (lane == 31) warp_sums[wid] = incl;
    __syncthreads();
    if (wid == 0) {
        int ws = warp_sums[lane];
#pragma unroll
        for (int d = 1; d < 32; d <<= 1) {
            int t = __shfl_up_sync(0xFFFFFFFFu, ws, d);
            if (lane >= d) ws += t;
        }
        warp_sums[lane] = ws;
    }
    __syncthreads();
    int excl = incl - v + (wid > 0 ? warp_sums[wid - 1] : 0);
    if (tid < CHUNK) g_offL[idx] = excl;
    if (tid == 0) g_bsum[blockIdx.x] = warp_sums[31];
}

// One warp: exclusive scan of the 25 chunk totals.
__global__ void k_scanB() {
    int lane = threadIdx.x;
    int v = (lane < NCHUNK) ? g_bsum[lane] : 0;
    int incl = v;
#pragma unroll
    for (int d = 1; d < 32; d <<= 1) {
        int t = __shfl_up_sync(0xFFFFFFFFu, incl, d);
        if (lane >= d) incl += t;
    }
    if (lane < NCHUNK) g_boff[lane] = incl - v;
}

// Scatter rowidx into CSR order — no atomics (rank precomputed).
__global__ void k_scatter() {
    int e = blockIdx.x * blockDim.x + threadIdx.x;
    if (e >= NE) return;
    int dst = g_dstv[e];
    int pos = g_offL[dst] + g_boff[dst / CHUNK] + g_lrank[e];
    g_csr[pos] = g_rowidx[e];
}

// Layer-1 aggregation: 16 threads per dst, register accumulation, unroll 8.
__global__ void k_agg1(const float* __restrict__ W1,
                       const float* __restrict__ root1,
                       const float* __restrict__ b1) {
    int g = blockIdx.x * (blockDim.x >> 4) + (threadIdx.x >> 4);
    int s = threadIdx.x & 15;
    if (g >= NN) return;
    int beg = final_off(g), end = final_off(g + 1);

    float4 acc = make_float4(0.f, 0.f, 0.f, 0.f);
    int i = beg;
    for (; i + 8 <= end; i += 8) {
        float4 v0 = __ldg((const float4*)(W1 + (long)g_csr[i + 0] * NH) + s);
        float4 v1 = __ldg((const float4*)(W1 + (long)g_csr[i + 1] * NH) + s);
        float4 v2 = __ldg((const float4*)(W1 + (long)g_csr[i + 2] * NH) + s);
        float4 v3 = __ldg((const float4*)(W1 + (long)g_csr[i + 3] * NH) + s);
        float4 v4 = __ldg((const float4*)(W1 + (long)g_csr[i + 4] * NH) + s);
        float4 v5 = __ldg((const float4*)(W1 + (long)g_csr[i + 5] * NH) + s);
        float4 v6 = __ldg((const float4*)(W1 + (long)g_csr[i + 6] * NH) + s);
        float4 v7 = __ldg((const float4*)(W1 + (long)g_csr[i + 7] * NH) + s);
        acc.x += (v0.x + v1.x) + (v2.x + v3.x) + (v4.x + v5.x) + (v6.x + v7.x);
        acc.y += (v0.y + v1.y) + (v2.y + v3.y) + (v4.y + v5.y) + (v6.y + v7.y);
        acc.z += (v0.z + v1.z) + (v2.z + v3.z) + (v4.z + v5.z) + (v6.z + v7.z);
        acc.w += (v0.w + v1.w) + (v2.w + v3.w) + (v4.w + v5.w) + (v6.w + v7.w);
    }
    for (; i < end; i++) {
        float4 v0 = __ldg((const float4*)(W1 + (long)g_csr[i] * NH) + s);
        acc.x += v0.x; acc.y += v0.y; acc.z += v0.z; acc.w += v0.w;
    }
    float4 rt = __ldg((const float4*)(root1 + (long)g * NH) + s);
    float4 bb = __ldg((const float4*)b1 + s);
    acc.x = fmaxf(acc.x + rt.x + bb.x, 0.f);
    acc.y = fmaxf(acc.y + rt.y + bb.y, 0.f);
    acc.z = fmaxf(acc.z + rt.z + bb.z, 0.f);
    acc.w = fmaxf(acc.w + rt.w + bb.w, 0.f);
    *((float4*)(g_x + (long)g * NH) + s) = acc;
}

// h[r, n, c] = sum_h x[n,h] * W2[r,h,c].  grid = (nodeTiles, NR).
__global__ void k_h(const float* __restrict__ W2) {
    __shared__ float w2s[NH * NC];
    int r = blockIdx.y;
    for (int i = threadIdx.x; i < NH * NC; i += blockDim.x)
        w2s[i] = W2[(long)r * NH * NC + i];
    __syncthreads();

    int c = threadIdx.x & 15;
    int n = blockIdx.x * 16 + (threadIdx.x >> 4);
    if (n >= NN) return;

    const float4* xr = (const float4*)(g_x + (long)n * NH);
    float acc = 0.0f;
#pragma unroll
    for (int h4 = 0; h4 < NH / 4; h4++) {
        float4 xv = __ldg(&xr[h4]);
        acc += xv.x * w2s[(h4 * 4 + 0) * NC + c];
        acc += xv.y * w2s[(h4 * 4 + 1) * NC + c];
        acc += xv.z * w2s[(h4 * 4 + 2) * NC + c];
        acc += xv.w * w2s[(h4 * 4 + 3) * NC + c];
    }
    g_h[((long)r * NN + n) * NC + c] = acc;
}

// Layer-2 aggregation + root + bias + log_softmax, fused. 16 threads per dst.
__global__ void k_agg2(const float* __restrict__ root2,
                       const float* __restrict__ b2,
                       float* __restrict__ out) {
    __shared__ float r2s[NH * NC];
    for (int i = threadIdx.x; i < NH * NC; i += blockDim.x) r2s[i] = root2[i];
    __syncthreads();

    int g = blockIdx.x * (blockDim.x >> 4) + (threadIdx.x >> 4);
    int c = threadIdx.x & 15;
    if (g >= NN) return;
    int beg = final_off(g), end = final_off(g + 1);

    float acc = __ldg(b2 + c);
    int i = beg;
    for (; i + 8 <= end; i += 8) {
        float v0 = __ldg(g_h + (long)g_csr[i + 0] * NC + c);
        float v1 = __ldg(g_h + (long)g_csr[i + 1] * NC + c);
        float v2 = __ldg(g_h + (long)g_csr[i + 2] * NC + c);
        float v3 = __ldg(g_h + (long)g_csr[i + 3] * NC + c);
        float v4 = __ldg(g_h + (long)g_csr[i + 4] * NC + c);
        float v5 = __ldg(g_h + (long)g_csr[i + 5] * NC + c);
        float v6 = __ldg(g_h + (long)g_csr[i + 6] * NC + c);
        float v7 = __ldg(g_h + (long)g_csr[i + 7] * NC + c);
        acc += ((v0 + v1) + (v2 + v3)) + ((v4 + v5) + (v6 + v7));
    }
    for (; i < end; i++)
        acc += __ldg(g_h + (long)g_csr[i] * NC + c);

    const float4* xr = (const float4*)(g_x + (long)g * NH);
#pragma unroll
    for (int h4 = 0; h4 < NH / 4; h4++) {
        float4 xv = __ldg(&xr[h4]);
        acc += xv.x * r2s[(h4 * 4 + 0) * NC + c];
        acc += xv.y * r2s[(h4 * 4 + 1) * NC + c];
        acc += xv.z * r2s[(h4 * 4 + 2) * NC + c];
        acc += xv.w * r2s[(h4 * 4 + 3) * NC + c];
    }

    unsigned mask = 0xFFFFu << (threadIdx.x & 16);
    float m = acc;
#pragma unroll
    for (int d = 8; d >= 1; d >>= 1) m = fmaxf(m, __shfl_xor_sync(mask, m, d));
    float ex = expf(acc - m);
    float sum = ex;
#pragma unroll
    for (int d = 8; d >= 1; d >>= 1) sum += __shfl_xor_sync(mask, sum, d);
    out[(long)g * NC + c] = acc - m - logf(sum);
}

extern "C" void kernel_launch(void* const* d_in, const int* in_sizes, int n_in,
                              void* d_out, int out_size) {
    const void*  edge_index = d_in[0];
    const void*  edge_type  = d_in[1];
    const float* W1         = (const float*)d_in[2];
    const float* root1      = (const float*)d_in[3];
    const float* b1         = (const float*)d_in[4];
    const float* W2         = (const float*)d_in[5];
    const float* root2      = (const float*)d_in[6];
    const float* b2         = (const float*)d_in[7];
    float* out = (float*)d_out;

    k_pre<<<(NN + 255) / 256 + 1, 256>>>(edge_index);
    k_convert<<<(NE + 255) / 256, 256>>>(edge_index, edge_type);
    k_scanA<<<NCHUNK, 1024>>>();
    k_scanB<<<1, 32>>>();
    k_scatter<<<(NE + 255) / 256, 256>>>();
    k_agg1<<<(NN * 16 + 255) / 256, 256>>>(W1, root1, b1);
    {
        dim3 grid((NN + 15) / 16, NR);
        k_h<<<grid, 256>>>(W2);
    }
    k_agg2<<<(NN * 16 + 255) / 256, 256>>>(root2, b2, out);
}

// round 5
// speedup vs baseline: 1.3889x; 1.2652x over previous
#include <cuda_runtime.h>
#include <cuda_bf16.h>

#define NN 25000
#define NR 16
#define NH 64
#define NC 16
#define NE 800000
#define CHUNK 1000          // NN = 25 * 1000
#define NCHUNK 25

// ---- scratch (allocation-free: __device__ globals) ----
__device__ float g_x[NN * NH];                 // layer-1 output x = relu(agg1+root1+b1)
__device__ float g_h[(size_t)NR * NN * NC];    // per-relation transformed nodes
__device__ int   g_rowidx[NE];                 // rel*NN + src (row into W1 and into h)
__device__ int   g_dstv[NE];
__device__ int   g_lrank[NE];                  // rank of edge within its dst bucket
__device__ int   g_deg[NN];
__device__ int   g_offL[NN];                   // chunk-local exclusive scan of deg
__device__ int   g_boff[NCHUNK];               // chunk base offsets
__device__ int   g_pref[NCHUNK];               // inclusive chunk prefix (internal)
__device__ volatile int g_flag[NCHUNK];        // chunk-done flags
__device__ int   g_is64;

__device__ __forceinline__ int final_off(int i) {
    return (i < NN) ? (g_offL[i] + g_boff[i / CHUNK]) : NE;
}

// ---------------------------------------------------------------------------
// Last block: dtype detect.  Other blocks: zero degree counters + scan flags.
__global__ void k_pre(const void* ei) {
    if (blockIdx.x == gridDim.x - 1) {
        if (threadIdx.x == 0) {
            const unsigned long long* p = (const unsigned long long*)ei;
            unsigned long long acc = 0;
#pragma unroll
            for (int i = 0; i < 64; i++) acc |= (p[i] >> 32);
            g_is64 = (acc == 0ull) ? 1 : 0;
        }
        return;
    }
    int i = blockIdx.x * blockDim.x + threadIdx.x;
    if (i < NN) g_deg[i] = 0;
    if (i < NCHUNK) g_flag[i] = 0;
}

// Convert edge metadata into packed ints + histogram dst degrees + bucket rank.
__global__ void k_convert(const void* ei, const void* et) {
    int e = blockIdx.x * blockDim.x + threadIdx.x;
    if (e >= NE) return;
    int src, dst, r;
    if (g_is64) {
        const long long* E = (const long long*)ei;
        const long long* T = (const long long*)et;
        src = (int)E[e]; dst = (int)E[NE + e]; r = (int)T[e];
    } else {
        const int* E = (const int*)ei;
        const int* T = (const int*)et;
        src = E[e]; dst = E[NE + e]; r = T[e];
    }
    g_rowidx[e] = r * NN + src;
    g_dstv[e]   = dst;
    g_lrank[e]  = atomicAdd(&g_deg[dst], 1);
}

// Single-pass scan: 25 blocks, local scan + chained prefix handoff.
__global__ void k_scan1() {
    __shared__ int warp_sums[32];
    __shared__ int s_total;
    int tid  = threadIdx.x;            // 1024 threads
    int lane = tid & 31;
    int wid  = tid >> 5;
    int b    = blockIdx.x;
    int idx  = b * CHUNK + tid;
    int v = (tid < CHUNK) ? g_deg[idx] : 0;
    int incl = v;
#pragma unroll
    for (int d = 1; d < 32; d <<= 1) {
        int t = __shfl_up_sync(0xFFFFFFFFu, incl, d);
        if (lane >= d) incl += t;
    }
    if (lane == 31) warp_sums[wid] = incl;
    __syncthreads();
    if (wid == 0) {
        int ws = warp_sums[lane];
#pragma unroll
        for (int d = 1; d < 32; d <<= 1) {
            int t = __shfl_up_sync(0xFFFFFFFFu, ws, d);
            if (lane >= d) ws += t;
        }
        warp_sums[lane] = ws;
        if (lane == 31) s_total = ws;
    }
    __syncthreads();
    int excl = incl - v + (wid > 0 ? warp_sums[wid - 1] : 0);
    if (tid < CHUNK) g_offL[idx] = excl;

    if (tid == 0) {
        int total = s_total;
        int pref;
        if (b == 0) {
            pref = 0;
        } else {
            while (g_flag[b - 1] == 0) { }
            __threadfence();
            pref = g_pref[b - 1];
        }
        g_boff[b] = pref;
        g_pref[b] = pref + total;
        __threadfence();
        g_flag[b] = 1;
    }
}

// Scatter rowidx into CSR order — no atomics (rank precomputed).
__global__ void k_scatter() {
    int e = blockIdx.x * blockDim.x + threadIdx.x;
    if (e >= NE) return;
    int dst = g_dstv[e];
    int pos = g_offL[dst] + g_boff[dst / CHUNK] + g_lrank[e];
    g_csr_store: ;
    g_lrank[e] = g_lrank[e];  // no-op to keep structure clear
    extern __device__ int g_csr[];
}

// (real scatter below — forward decl workaround removed)
__device__ int g_csr[NE];
__global__ void k_scatter2() {
    int e = blockIdx.x * blockDim.x + threadIdx.x;
    if (e >= NE) return;
    int dst = g_dstv[e];
    int pos = g_offL[dst] + g_boff[dst / CHUNK] + g_lrank[e];
    g_csr[pos] = g_rowidx[e];
}

// Layer-1 aggregation: 16 threads per dst, register accumulation, unroll 8.
__global__ void k_agg1(const float* __restrict__ W1,
                       const float* __restrict__ root1,
                       const float* __restrict__ b1) {
    int g = blockIdx.x * (blockDim.x >> 4) + (threadIdx.x >> 4);
    int s = threadIdx.x & 15;
    if (g >= NN) return;
    int beg = final_off(g), end = final_off(g + 1);

    float4 acc = make_float4(0.f, 0.f, 0.f, 0.f);
    int i = beg;
    for (; i + 8 <= end; i += 8) {
        float4 v0 = __ldg((const float4*)(W1 + (long)g_csr[i + 0] * NH) + s);
        float4 v1 = __ldg((const float4*)(W1 + (long)g_csr[i + 1] * NH) + s);
        float4 v2 = __ldg((const float4*)(W1 + (long)g_csr[i + 2] * NH) + s);
        float4 v3 = __ldg((const float4*)(W1 + (long)g_csr[i + 3] * NH) + s);
        float4 v4 = __ldg((const float4*)(W1 + (long)g_csr[i + 4] * NH) + s);
        float4 v5 = __ldg((const float4*)(W1 + (long)g_csr[i + 5] * NH) + s);
        float4 v6 = __ldg((const float4*)(W1 + (long)g_csr[i + 6] * NH) + s);
        float4 v7 = __ldg((const float4*)(W1 + (long)g_csr[i + 7] * NH) + s);
        acc.x += (v0.x + v1.x) + (v2.x + v3.x) + (v4.x + v5.x) + (v6.x + v7.x);
        acc.y += (v0.y + v1.y) + (v2.y + v3.y) + (v4.y + v5.y) + (v6.y + v7.y);
        acc.z += (v0.z + v1.z) + (v2.z + v3.z) + (v4.z + v5.z) + (v6.z + v7.z);
        acc.w += (v0.w + v1.w) + (v2.w + v3.w) + (v4.w + v5.w) + (v6.w + v7.w);
    }
    for (; i < end; i++) {
        float4 v0 = __ldg((const float4*)(W1 + (long)g_csr[i] * NH) + s);
        acc.x += v0.x; acc.y += v0.y; acc.z += v0.z; acc.w += v0.w;
    }
    float4 rt = __ldg((const float4*)(root1 + (long)g * NH) + s);
    float4 bb = __ldg((const float4*)b1 + s);
    acc.x = fmaxf(acc.x + rt.x + bb.x, 0.f);
    acc.y = fmaxf(acc.y + rt.y + bb.y, 0.f);
    acc.z = fmaxf(acc.z + rt.z + bb.z, 0.f);
    acc.w = fmaxf(acc.w + rt.w + bb.w, 0.f);
    *((float4*)(g_x + (long)g * NH) + s) = acc;
}

// ---------------------------------------------------------------------------
// h[r,n,c] = sum_h x[n,h] * W2[r,h,c]  — f32x2 version.
// Block = 256 threads = 8 warps; warp w covers relations {2w, 2w+1}.
// Thread: r = 2w + (lane>>4), c = lane&15.  W2 column held in regs as 32
// f32x2 pairs over h.  x staged per 64-node tile in shared, read as b64.
#define HT 64   // nodes per tile
__global__ void __launch_bounds__(256) k_h2(const float* __restrict__ W2) {
    __shared__ unsigned long long xs[HT * (NH / 2)];   // 16 KB

    int tid  = threadIdx.x;
    int lane = tid & 31;
    int w    = tid >> 5;
    int r    = w * 2 + (lane >> 4);
    int c    = lane & 15;

    // Pack W2 column (r, :, c) into 32 f32x2 registers (pairs over h).
    unsigned long long wp[NH / 2];
    const float* w2r = W2 + (long)r * NH * NC + c;
#pragma unroll
    for (int j = 0; j < NH / 2; j++) {
        float we = __ldg(w2r + (2 * j) * NC);
        float wo = __ldg(w2r + (2 * j + 1) * NC);
        asm("mov.b64 %0, {%1, %2};" : "=l"(wp[j]) : "f"(we), "f"(wo));
    }

    int tile = blockIdx.x;
    int nbase = tile * HT;
    // Stage x tile into shared (as 64-bit words).
    const unsigned long long* gx8 = (const unsigned long long*)g_x;
    long gbase = (long)nbase * (NH / 2);
    for (int i = tid; i < HT * (NH / 2); i += 256) {
        long gi = gbase + i;
        xs[i] = (gi < (long)NN * (NH / 2)) ? gx8[gi] : 0ull;
    }
    __syncthreads();

    int nvalid = NN - nbase; if (nvalid > HT) nvalid = HT;
    for (int j = 0; j < nvalid; j++) {
        const unsigned long long* xrow = xs + j * (NH / 2);
        unsigned long long a0 = 0ull, a1 = 0ull;
#pragma unroll
        for (int k = 0; k < NH / 4; k++) {
            unsigned long long x0 = xrow[2 * k];
            unsigned long long x1 = xrow[2 * k + 1];
            asm("fma.rn.f32x2 %0, %1, %2, %0;" : "+l"(a0) : "l"(x0), "l"(wp[2 * k]));
            asm("fma.rn.f32x2 %0, %1, %2, %0;" : "+l"(a1) : "l"(x1), "l"(wp[2 * k + 1]));
        }
        unsigned long long asum;
        asm("add.rn.f32x2 %0, %1, %2;" : "=l"(asum) : "l"(a0), "l"(a1));
        float lo, hi;
        asm("mov.b64 {%0, %1}, %2;" : "=f"(lo), "=f"(hi) : "l"(asum));
        g_h[((long)r * NN + (nbase + j)) * NC + c] = lo + hi;
    }
}

// Layer-2 aggregation + root + bias + log_softmax, fused. 16 threads per dst.
__global__ void k_agg2(const float* __restrict__ root2,
                       const float* __restrict__ b2,
                       float* __restrict__ out) {
    __shared__ float r2s[NH * NC];
    for (int i = threadIdx.x; i < NH * NC; i += blockDim.x) r2s[i] = root2[i];
    __syncthreads();

    int g = blockIdx.x * (blockDim.x >> 4) + (threadIdx.x >> 4);
    int c = threadIdx.x & 15;
    if (g >= NN) return;
    int beg = final_off(g), end = final_off(g + 1);

    float acc = __ldg(b2 + c);
    int i = beg;
    for (; i + 8 <= end; i += 8) {
        float v0 = __ldg(g_h + (long)g_csr[i + 0] * NC + c);
        float v1 = __ldg(g_h + (long)g_csr[i + 1] * NC + c);
        float v2 = __ldg(g_h + (long)g_csr[i + 2] * NC + c);
        float v3 = __ldg(g_h + (long)g_csr[i + 3] * NC + c);
        float v4 = __ldg(g_h + (long)g_csr[i + 4] * NC + c);
        float v5 = __ldg(g_h + (long)g_csr[i + 5] * NC + c);
        float v6 = __ldg(g_h + (long)g_csr[i + 6] * NC + c);
        float v7 = __ldg(g_h + (long)g_csr[i + 7] * NC + c);
        acc += ((v0 + v1) + (v2 + v3)) + ((v4 + v5) + (v6 + v7));
    }
    for (; i < end; i++)
        acc += __ldg(g_h + (long)g_csr[i] * NC + c);

    const float4* xr = (const float4*)(g_x + (long)g * NH);
#pragma unroll
    for (int h4 = 0; h4 < NH / 4; h4++) {
        float4 xv = __ldg(&xr[h4]);
        acc += xv.x * r2s[(h4 * 4 + 0) * NC + c];
        acc += xv.y * r2s[(h4 * 4 + 1) * NC + c];
        acc += xv.z * r2s[(h4 * 4 + 2) * NC + c];
        acc += xv.w * r2s[(h4 * 4 + 3) * NC + c];
    }

    unsigned mask = 0xFFFFu << (threadIdx.x & 16);
    float m = acc;
#pragma unroll
    for (int d = 8; d >= 1; d >>= 1) m = fmaxf(m, __shfl_xor_sync(mask, m, d));
    float ex = expf(acc - m);
    float sum = ex;
#pragma unroll
    for (int d = 8; d >= 1; d >>= 1) sum += __shfl_xor_sync(mask, sum, d);
    out[(long)g * NC + c] = acc - m - logf(sum);
}

extern "C" void kernel_launch(void* const* d_in, const int* in_sizes, int n_in,
                              void* d_out, int out_size) {
    const void*  edge_index = d_in[0];
    const void*  edge_type  = d_in[1];
    const float* W1         = (const float*)d_in[2];
    const float* root1      = (const float*)d_in[3];
    const float* b1         = (const float*)d_in[4];
    const float* W2         = (const float*)d_in[5];
    const float* root2      = (const float*)d_in[6];
    const float* b2         = (const float*)d_in[7];
    float* out = (float*)d_out;

    k_pre<<<(NN + 255) / 256 + 1, 256>>>(edge_index);
    k_convert<<<(NE + 255) / 256, 256>>>(edge_index, edge_type);
    k_scan1<<<NCHUNK, 1024>>>();
    k_scatter2<<<(NE + 255) / 256, 256>>>();
    k_agg1<<<(NN * 16 + 255) / 256, 256>>>(W1, root1, b1);
    k_h2<<<(NN + HT - 1) / HT, 256>>>(W2);
    k_agg2<<<(NN * 16 + 255) / 256, 256>>>(root2, b2, out);
}

// round 6
// speedup vs baseline: 1.4085x; 1.0141x over previous
#include <cuda_runtime.h>
#include <cuda_bf16.h>

#define NN 25000
#define NR 16
#define NH 64
#define NC 16
#define NE 800000
#define CHUNK 1000          // NN = 25 * 1000
#define NCHUNK 25

// ---- scratch (allocation-free: __device__ globals) ----
__device__ float g_x[NN * NH];                 // layer-1 output x = relu(agg1+root1+b1)
__device__ float g_h[(size_t)NR * NN * NC];    // per-relation transformed nodes
__device__ int   g_rowidx[NE];                 // rel*NN + src (row into W1 and into h)
__device__ int   g_dstv[NE];
__device__ int   g_lrank[NE];                  // rank of edge within its dst bucket
__device__ int   g_deg[NN];
__device__ int   g_offL[NN];                   // chunk-local exclusive scan of deg
__device__ int   g_boff[NCHUNK];               // chunk base offsets
__device__ int   g_pref[NCHUNK];               // inclusive chunk prefix (internal)
__device__ volatile int g_flag[NCHUNK];        // chunk-done flags
__device__ int   g_is64;

__device__ __forceinline__ int final_off(int i) {
    return (i < NN) ? (g_offL[i] + g_boff[i / CHUNK]) : NE;
}

// ---------------------------------------------------------------------------
// Last block: dtype detect.  Other blocks: zero degree counters + scan flags.
__global__ void k_pre(const void* ei) {
    if (blockIdx.x == gridDim.x - 1) {
        if (threadIdx.x == 0) {
            const unsigned long long* p = (const unsigned long long*)ei;
            unsigned long long acc = 0;
#pragma unroll
            for (int i = 0; i < 64; i++) acc |= (p[i] >> 32);
            g_is64 = (acc == 0ull) ? 1 : 0;
        }
        return;
    }
    int i = blockIdx.x * blockDim.x + threadIdx.x;
    if (i < NN) g_deg[i] = 0;
    if (i < NCHUNK) g_flag[i] = 0;
}

// Convert edge metadata into packed ints + histogram dst degrees + bucket rank.
__global__ void k_convert(const void* ei, const void* et) {
    int e = blockIdx.x * blockDim.x + threadIdx.x;
    if (e >= NE) return;
    int src, dst, r;
    if (g_is64) {
        const long long* E = (const long long*)ei;
        const long long* T = (const long long*)et;
        src = (int)E[e]; dst = (int)E[NE + e]; r = (int)T[e];
    } else {
        const int* E = (const int*)ei;
        const int* T = (const int*)et;
        src = E[e]; dst = E[NE + e]; r = T[e];
    }
    g_rowidx[e] = r * NN + src;
    g_dstv[e]   = dst;
    g_lrank[e]  = atomicAdd(&g_deg[dst], 1);
}

// Single-pass scan: 25 blocks, local scan + chained prefix handoff.
__global__ void k_scan1() {
    __shared__ int warp_sums[32];
    __shared__ int s_total;
    int tid  = threadIdx.x;            // 1024 threads
    int lane = tid & 31;
    int wid  = tid >> 5;
    int b    = blockIdx.x;
    int idx  = b * CHUNK + tid;
    int v = (tid < CHUNK) ? g_deg[idx] : 0;
    int incl = v;
#pragma unroll
    for (int d = 1; d < 32; d <<= 1) {
        int t = __shfl_up_sync(0xFFFFFFFFu, incl, d);
        if (lane >= d) incl += t;
    }
    if (lane == 31) warp_sums[wid] = incl;
    __syncthreads();
    if (wid == 0) {
        int ws = warp_sums[lane];
#pragma unroll
        for (int d = 1; d < 32; d <<= 1) {
            int t = __shfl_up_sync(0xFFFFFFFFu, ws, d);
            if (lane >= d) ws += t;
        }
        warp_sums[lane] = ws;
        if (lane == 31) s_total = ws;
    }
    __syncthreads();
    int excl = incl - v + (wid > 0 ? warp_sums[wid - 1] : 0);
    if (tid < CHUNK) g_offL[idx] = excl;

    if (tid == 0) {
        int total = s_total;
        int pref;
        if (b == 0) {
            pref = 0;
        } else {
            while (g_flag[b - 1] == 0) { }
            __threadfence();
            pref = g_pref[b - 1];
        }
        g_boff[b] = pref;
        g_pref[b] = pref + total;
        __threadfence();
        g_flag[b] = 1;
    }
}

// Scatter rowidx into CSR order — no atomics (rank precomputed).
__global__ void k_scatter() {
    int e = blockIdx.x * blockDim.x + threadIdx.x;
    if (e >= NE) return;
    int dst = g_dstv[e];
    int pos = g_offL[dst] + g_boff[dst / CHUNK] + g_lrank[e];
    g_csr_store: ;
    g_lrank[e] = g_lrank[e];  // no-op to keep structure clear
    extern __device__ int g_csr[];
}

// (real scatter below — forward decl workaround removed)
__device__ int g_csr[NE];
__global__ void k_scatter2() {
    int e = blockIdx.x * blockDim.x + threadIdx.x;
    if (e >= NE) return;
    int dst = g_dstv[e];
    int pos = g_offL[dst] + g_boff[dst / CHUNK] + g_lrank[e];
    g_csr[pos] = g_rowidx[e];
}

// Layer-1 aggregation: 16 threads per dst, register accumulation, unroll 8.
__global__ void k_agg1(const float* __restrict__ W1,
                       const float* __restrict__ root1,
                       const float* __restrict__ b1) {
    int g = blockIdx.x * (blockDim.x >> 4) + (threadIdx.x >> 4);
    int s = threadIdx.x & 15;
    if (g >= NN) return;
    int beg = final_off(g), end = final_off(g + 1);

    float4 acc = make_float4(0.f, 0.f, 0.f, 0.f);
    int i = beg;
    for (; i + 8 <= end; i += 8) {
        float4 v0 = __ldg((const float4*)(W1 + (long)g_csr[i + 0] * NH) + s);
        float4 v1 = __ldg((const float4*)(W1 + (long)g_csr[i + 1] * NH) + s);
        float4 v2 = __ldg((const float4*)(W1 + (long)g_csr[i + 2] * NH) + s);
        float4 v3 = __ldg((const float4*)(W1 + (long)g_csr[i + 3] * NH) + s);
        float4 v4 = __ldg((const float4*)(W1 + (long)g_csr[i + 4] * NH) + s);
        float4 v5 = __ldg((const float4*)(W1 + (long)g_csr[i + 5] * NH) + s);
        float4 v6 = __ldg((const float4*)(W1 + (long)g_csr[i + 6] * NH) + s);
        float4 v7 = __ldg((const float4*)(W1 + (long)g_csr[i + 7] * NH) + s);
        acc.x += (v0.x + v1.x) + (v2.x + v3.x) + (v4.x + v5.x) + (v6.x + v7.x);
        acc.y += (v0.y + v1.y) + (v2.y + v3.y) + (v4.y + v5.y) + (v6.y + v7.y);
        acc.z += (v0.z + v1.z) + (v2.z + v3.z) + (v4.z + v5.z) + (v6.z + v7.z);
        acc.w += (v0.w + v1.w) + (v2.w + v3.w) + (v4.w + v5.w) + (v6.w + v7.w);
    }
    for (; i < end; i++) {
        float4 v0 = __ldg((const float4*)(W1 + (long)g_csr[i] * NH) + s);
        acc.x += v0.x; acc.y += v0.y; acc.z += v0.z; acc.w += v0.w;
    }
    float4 rt = __ldg((const float4*)(root1 + (long)g * NH) + s);
    float4 bb = __ldg((const float4*)b1 + s);
    acc.x = fmaxf(acc.x + rt.x + bb.x, 0.f);
    acc.y = fmaxf(acc.y + rt.y + bb.y, 0.f);
    acc.z = fmaxf(acc.z + rt.z + bb.z, 0.f);
    acc.w = fmaxf(acc.w + rt.w + bb.w, 0.f);
    *((float4*)(g_x + (long)g * NH) + s) = acc;
}

// ---------------------------------------------------------------------------
// h[r,n,c] = sum_h x[n,h] * W2[r,h,c]  — f32x2 version.
// Block = 256 threads = 8 warps; warp w covers relations {2w, 2w+1}.
// Thread: r = 2w + (lane>>4), c = lane&15.  W2 column held in regs as 32
// f32x2 pairs over h.  x staged per 64-node tile in shared, read as b64.
#define HT 64   // nodes per tile
__global__ void __launch_bounds__(256) k_h2(const float* __restrict__ W2) {
    __shared__ unsigned long long xs[HT * (NH / 2)];   // 16 KB

    int tid  = threadIdx.x;
    int lane = tid & 31;
    int w    = tid >> 5;
    int r    = w * 2 + (lane >> 4);
    int c    = lane & 15;

    // Pack W2 column (r, :, c) into 32 f32x2 registers (pairs over h).
    unsigned long long wp[NH / 2];
    const float* w2r = W2 + (long)r * NH * NC + c;
#pragma unroll
    for (int j = 0; j < NH / 2; j++) {
        float we = __ldg(w2r + (2 * j) * NC);
        float wo = __ldg(w2r + (2 * j + 1) * NC);
        asm("mov.b64 %0, {%1, %2};" : "=l"(wp[j]) : "f"(we), "f"(wo));
    }

    int tile = blockIdx.x;
    int nbase = tile * HT;
    // Stage x tile into shared (as 64-bit words).
    const unsigned long long* gx8 = (const unsigned long long*)g_x;
    long gbase = (long)nbase * (NH / 2);
    for (int i = tid; i < HT * (NH / 2); i += 256) {
        long gi = gbase + i;
        xs[i] = (gi < (long)NN * (NH / 2)) ? gx8[gi] : 0ull;
    }
    __syncthreads();

    int nvalid = NN - nbase; if (nvalid > HT) nvalid = HT;
    for (int j = 0; j < nvalid; j++) {
        const unsigned long long* xrow = xs + j * (NH / 2);
        unsigned long long a0 = 0ull, a1 = 0ull;
#pragma unroll
        for (int k = 0; k < NH / 4; k++) {
            unsigned long long x0 = xrow[2 * k];
            unsigned long long x1 = xrow[2 * k + 1];
            asm("fma.rn.f32x2 %0, %1, %2, %0;" : "+l"(a0) : "l"(x0), "l"(wp[2 * k]));
            asm("fma.rn.f32x2 %0, %1, %2, %0;" : "+l"(a1) : "l"(x1), "l"(wp[2 * k + 1]));
        }
        unsigned long long asum;
        asm("add.rn.f32x2 %0, %1, %2;" : "=l"(asum) : "l"(a0), "l"(a1));
        float lo, hi;
        asm("mov.b64 {%0, %1}, %2;" : "=f"(lo), "=f"(hi) : "l"(asum));
        g_h[((long)r * NN + (nbase + j)) * NC + c] = lo + hi;
    }
}

// Layer-2 aggregation + root + bias + log_softmax, fused. 16 threads per dst.
__global__ void k_agg2(const float* __restrict__ root2,
                       const float* __restrict__ b2,
                       float* __restrict__ out) {
    __shared__ float r2s[NH * NC];
    for (int i = threadIdx.x; i < NH * NC; i += blockDim.x) r2s[i] = root2[i];
    __syncthreads();

    int g = blockIdx.x * (blockDim.x >> 4) + (threadIdx.x >> 4);
    int c = threadIdx.x & 15;
    if (g >= NN) return;
    int beg = final_off(g), end = final_off(g + 1);

    float acc = __ldg(b2 + c);
    int i = beg;
    for (; i + 8 <= end; i += 8) {
        float v0 = __ldg(g_h + (long)g_csr[i + 0] * NC + c);
        float v1 = __ldg(g_h + (long)g_csr[i + 1] * NC + c);
        float v2 = __ldg(g_h + (long)g_csr[i + 2] * NC + c);
        float v3 = __ldg(g_h + (long)g_csr[i + 3] * NC + c);
        float v4 = __ldg(g_h + (long)g_csr[i + 4] * NC + c);
        float v5 = __ldg(g_h + (long)g_csr[i + 5] * NC + c);
        float v6 = __ldg(g_h + (long)g_csr[i + 6] * NC + c);
        float v7 = __ldg(g_h + (long)g_csr[i + 7] * NC + c);
        acc += ((v0 + v1) + (v2 + v3)) + ((v4 + v5) + (v6 + v7));
    }
    for (; i < end; i++)
        acc += __ldg(g_h + (long)g_csr[i] * NC + c);

    const float4* xr = (const float4*)(g_x + (long)g * NH);
#pragma unroll
    for (int h4 = 0; h4 < NH / 4; h4++) {
        float4 xv = __ldg(&xr[h4]);
        acc += xv.x * r2s[(h4 * 4 + 0) * NC + c];
        acc += xv.y * r2s[(h4 * 4 + 1) * NC + c];
        acc += xv.z * r2s[(h4 * 4 + 2) * NC + c];
        acc += xv.w * r2s[(h4 * 4 + 3) * NC + c];
    }

    unsigned mask = 0xFFFFu << (threadIdx.x & 16);
    float m = acc;
#pragma unroll
    for (int d = 8; d >= 1; d >>= 1) m = fmaxf(m, __shfl_xor_sync(mask, m, d));
    float ex = expf(acc - m);
    float sum = ex;
#pragma unroll
    for (int d = 8; d >= 1; d >>= 1) sum += __shfl_xor_sync(mask, sum, d);
    out[(long)g * NC + c] = acc - m - logf(sum);
}

extern "C" void kernel_launch(void* const* d_in, const int* in_sizes, int n_in,
                              void* d_out, int out_size) {
    const void*  edge_index = d_in[0];
    const void*  edge_type  = d_in[1];
    const float* W1         = (const float*)d_in[2];
    const float* root1      = (const float*)d_in[3];
    const float* b1         = (const float*)d_in[4];
    const float* W2         = (const float*)d_in[5];
    const float* root2      = (const float*)d_in[6];
    const float* b2         = (const float*)d_in[7];
    float* out = (float*)d_out;

    k_pre<<<(NN + 255) / 256 + 1, 256>>>(edge_index);
    k_convert<<<(NE + 255) / 256, 256>>>(edge_index, edge_type);
    k_scan1<<<NCHUNK, 1024>>>();
    k_scatter2<<<(NE + 255) / 256, 256>>>();
    k_agg1<<<(NN * 16 + 255) / 256, 256>>>(W1, root1, b1);
    k_h2<<<(NN + HT - 1) / HT, 256>>>(W2);
    k_agg2<<<(NN * 16 + 255) / 256, 256>>>(root2, b2, out);
}